// round 5
// baseline (speedup 1.0000x reference)
#include <cuda_runtime.h>
#include <cuda_bf16.h>
#include <math_constants.h>

#define B_  8
#define SQ_ 128
#define SK_ 1024
#define U_  256

// Scratch for projected q and k (allocation-free rule: __device__ globals)
__device__ float g_q[B_ * SQ_ * U_];   // 1 MB
__device__ float g_k[B_ * SK_ * U_];   // 8 MB

// Packed f16x2 tanh: s0,s1 computed in fp32 (exact), rounded to f16 only as
// the tanh argument. MUFU lanes halved vs tanh.approx.f32.
// Pack order: cvt.rn.f16x2.f32 d, a, b  ->  d.hi = cvt(a), d.lo = cvt(b).
__device__ __forceinline__ void tanh2_acc(float s0, float s1, float w0, float w1,
                                          float& acc) {
    unsigned h, t;
    asm("cvt.rn.f16x2.f32 %0, %1, %2;" : "=r"(h) : "f"(s1), "f"(s0));
    asm("tanh.approx.f16x2 %0, %1;" : "=r"(t) : "r"(h));
    float t0, t1;
    asm("{\n\t"
        ".reg .b16 lo, hi;\n\t"
        "mov.b32 {lo, hi}, %2;\n\t"
        "cvt.f32.f16 %0, lo;\n\t"
        "cvt.f32.f16 %1, hi;\n\t"
        "}" : "=f"(t0), "=f"(t1) : "r"(t));
    acc = fmaf(t0, w0, fmaf(t1, w1, acc));
}

// ---------------------------------------------------------------------------
// 64x64 register-tiled SGEMM (k-projection): C = A @ B, 256 thr, 4x4 micro.
// ---------------------------------------------------------------------------
__global__ void gemm_tiled(const float* __restrict__ A, const float* __restrict__ Bm,
                           float* __restrict__ C, int M, int N, int K) {
    __shared__ float As[16][68];
    __shared__ float Bs[16][64];

    const int tid = threadIdx.x;
    const int tx = tid & 15;
    const int ty = tid >> 4;
    const int m0 = blockIdx.y * 64;
    const int n0 = blockIdx.x * 64;

    const int arow = tid >> 2;
    const int acol = (tid & 3) << 2;
    const int brow = tid >> 4;
    const int bcol = (tid & 15) << 2;

    float acc[4][4];
#pragma unroll
    for (int r = 0; r < 4; r++)
#pragma unroll
        for (int c = 0; c < 4; c++) acc[r][c] = 0.0f;

    for (int k0 = 0; k0 < K; k0 += 16) {
        float4 av = *(const float4*)&A[(long long)(m0 + arow) * K + k0 + acol];
        float4 bv = *(const float4*)&Bm[(long long)(k0 + brow) * N + n0 + bcol];
        As[acol + 0][arow] = av.x;
        As[acol + 1][arow] = av.y;
        As[acol + 2][arow] = av.z;
        As[acol + 3][arow] = av.w;
        *(float4*)&Bs[brow][bcol] = bv;
        __syncthreads();
#pragma unroll
        for (int k = 0; k < 16; k++) {
            float4 a4 = *(const float4*)&As[k][ty << 2];
            float4 b4 = *(const float4*)&Bs[k][tx << 2];
            float ar[4] = {a4.x, a4.y, a4.z, a4.w};
            float br[4] = {b4.x, b4.y, b4.z, b4.w};
#pragma unroll
            for (int r = 0; r < 4; r++)
#pragma unroll
                for (int c = 0; c < 4; c++) acc[r][c] += ar[r] * br[c];
        }
        __syncthreads();
    }

#pragma unroll
    for (int r = 0; r < 4; r++) {
        float4 o = make_float4(acc[r][0], acc[r][1], acc[r][2], acc[r][3]);
        *(float4*)&C[(long long)(m0 + (ty << 2) + r) * N + n0 + (tx << 2)] = o;
    }
}

// ---------------------------------------------------------------------------
// 32x64-tile SGEMM (q-projection + context). Batched via blockIdx.z strides.
// ---------------------------------------------------------------------------
__global__ void gemm_32x64(const float* __restrict__ A, const float* __restrict__ Bm,
                           float* __restrict__ C, int M, int N, int K,
                           long long sA, long long sB, long long sC) {
    A  += (long long)blockIdx.z * sA;
    Bm += (long long)blockIdx.z * sB;
    C  += (long long)blockIdx.z * sC;

    __shared__ float As[16][34];
    __shared__ float Bs[16][64];

    const int tid = threadIdx.x;
    const int tx = tid & 15;
    const int ty = tid >> 4;
    const int m0 = blockIdx.y * 32;
    const int n0 = blockIdx.x * 64;

    const int arow = tid >> 3;
    const int acol = (tid & 7) << 1;
    const int brow = tid >> 4;
    const int bcol = (tid & 15) << 2;

    float acc0[4] = {0.f, 0.f, 0.f, 0.f};
    float acc1[4] = {0.f, 0.f, 0.f, 0.f};

    for (int k0 = 0; k0 < K; k0 += 16) {
        float2 av = *(const float2*)&A[(long long)(m0 + arow) * K + k0 + acol];
        float4 bv = *(const float4*)&Bm[(long long)(k0 + brow) * N + n0 + bcol];
        As[acol + 0][arow] = av.x;
        As[acol + 1][arow] = av.y;
        *(float4*)&Bs[brow][bcol] = bv;
        __syncthreads();
#pragma unroll
        for (int k = 0; k < 16; k++) {
            float a0 = As[k][(ty << 1) + 0];
            float a1 = As[k][(ty << 1) + 1];
            float4 b4 = *(const float4*)&Bs[k][tx << 2];
            acc0[0] += a0 * b4.x; acc0[1] += a0 * b4.y;
            acc0[2] += a0 * b4.z; acc0[3] += a0 * b4.w;
            acc1[0] += a1 * b4.x; acc1[1] += a1 * b4.y;
            acc1[2] += a1 * b4.z; acc1[3] += a1 * b4.w;
        }
        __syncthreads();
    }

    *(float4*)&C[(long long)(m0 + (ty << 1) + 0) * N + n0 + (tx << 2)] =
        make_float4(acc0[0], acc0[1], acc0[2], acc0[3]);
    *(float4*)&C[(long long)(m0 + (ty << 1) + 1) * N + n0 + (tx << 2)] =
        make_float4(acc1[0], acc1[1], acc1[2], acc1[3]);
}

// ---------------------------------------------------------------------------
// Scores v3: j-column per thread, k in registers (double-buffered), q via
// broadcast LDS, tanh via packed f16x2 (2 elements / MUFU lane).
// score[b,i,j] = sum_u tanh(q[b,i,u] + k[b,j,u]) * wv[u]
// ---------------------------------------------------------------------------
#define TQ 16

__global__ void scores_kernel(const float* __restrict__ wv, float* __restrict__ attn) {
    const int b  = blockIdx.z;
    const int ib = blockIdx.y;
    const int tid = threadIdx.x;
    const int j  = blockIdx.x * 256 + tid;

    __shared__ float qs[TQ][U_];   // 16 KB
    __shared__ float wvs[U_];

    const float* qbase = g_q + ((long long)(b * SQ_ + ib * TQ)) * U_;
#pragma unroll
    for (int l = 0; l < 4; l++) {
        int idx = tid + l * 256;
        int row = idx >> 6;
        int col = (idx & 63) << 2;
        *(float4*)&qs[row][col] = *(const float4*)&qbase[(long long)row * U_ + col];
    }
    if (tid < 64) *(float4*)&wvs[tid << 2] = *(const float4*)&wv[tid << 2];
    __syncthreads();

    const float* kp = g_k + ((long long)(b * SK_) + j) * U_;

    float acc[TQ];
#pragma unroll
    for (int i = 0; i < TQ; i++) acc[i] = 0.0f;

    float4 ka = *(const float4*)&kp[0];
    float4 kb = *(const float4*)&kp[4];

#pragma unroll 4
    for (int uc = 0; uc < U_; uc += 8) {
        int un = (uc + 8 < U_) ? uc + 8 : uc;   // clamped tail prefetch
        float4 kna = *(const float4*)&kp[un];
        float4 knb = *(const float4*)&kp[un + 4];
        float4 w0 = *(const float4*)&wvs[uc];
        float4 w1 = *(const float4*)&wvs[uc + 4];
#pragma unroll
        for (int i = 0; i < TQ; i++) {
            float4 q0 = *(const float4*)&qs[i][uc];        // broadcast LDS
            float4 q1 = *(const float4*)&qs[i][uc + 4];    // broadcast LDS
            float a = acc[i];
            tanh2_acc(q0.x + ka.x, q0.y + ka.y, w0.x, w0.y, a);
            tanh2_acc(q0.z + ka.z, q0.w + ka.w, w0.z, w0.w, a);
            tanh2_acc(q1.x + kb.x, q1.y + kb.y, w1.x, w1.y, a);
            tanh2_acc(q1.z + kb.z, q1.w + kb.w, w1.z, w1.w, a);
            acc[i] = a;
        }
        ka = kna;
        kb = knb;
    }

    long long base = ((long long)(b * SQ_ + ib * TQ)) * SK_ + j;
#pragma unroll
    for (int i = 0; i < TQ; i++) attn[base + (long long)i * SK_] = acc[i];
}

// ---------------------------------------------------------------------------
// Row softmax over SK=1024, in place. One CTA (256 threads) per (b,i) row.
// ---------------------------------------------------------------------------
__global__ void softmax_kernel(float* __restrict__ attn) {
    float* p = attn + (long long)blockIdx.x * SK_;
    const int tid = threadIdx.x;
    __shared__ float red[8];

    float4 x = *(const float4*)&p[tid << 2];
    float m = fmaxf(fmaxf(x.x, x.y), fmaxf(x.z, x.w));
#pragma unroll
    for (int o = 16; o; o >>= 1) m = fmaxf(m, __shfl_xor_sync(0xffffffffu, m, o));
    if ((tid & 31) == 0) red[tid >> 5] = m;
    __syncthreads();
    float M = red[0];
#pragma unroll
    for (int w = 1; w < 8; w++) M = fmaxf(M, red[w]);

    float4 e;
    e.x = __expf(x.x - M);
    e.y = __expf(x.y - M);
    e.z = __expf(x.z - M);
    e.w = __expf(x.w - M);
    float s = (e.x + e.y) + (e.z + e.w);
#pragma unroll
    for (int o = 16; o; o >>= 1) s += __shfl_xor_sync(0xffffffffu, s, o);
    __syncthreads();
    if ((tid & 31) == 0) red[tid >> 5] = s;
    __syncthreads();
    float S = 0.f;
#pragma unroll
    for (int w = 0; w < 8; w++) S += red[w];
    float inv = 1.0f / S;
    e.x *= inv; e.y *= inv; e.z *= inv; e.w *= inv;
    *(float4*)&p[tid << 2] = e;
}

// ---------------------------------------------------------------------------
extern "C" void kernel_launch(void* const* d_in, const int* in_sizes, int n_in,
                              void* d_out, int out_size) {
    const float* query = (const float*)d_in[0];
    const float* key   = (const float*)d_in[1];
    const float* value = (const float*)d_in[2];
    const float* Wq    = (const float*)d_in[3];
    const float* Wk    = (const float*)d_in[4];
    const float* wv    = (const float*)d_in[5];

    float* out  = (float*)d_out;
    float* ctx  = out;                            // [B, SQ, U]
    float* attn = out + (long long)B_ * SQ_ * U_; // [B, SQ, SK]

    void* pq = nullptr; void* pk = nullptr;
    cudaGetSymbolAddress(&pq, g_q);
    cudaGetSymbolAddress(&pk, g_k);
    float* dq = (float*)pq;
    float* dk = (float*)pk;

    // 1) Projections
    gemm_32x64<<<dim3(U_ / 64, (B_ * SQ_) / 32, 1), 256>>>(
        query, Wq, dq, B_ * SQ_, U_, U_, 0, 0, 0);
    gemm_tiled<<<dim3(U_ / 64, (B_ * SK_) / 64, 1), 256>>>(
        key, Wk, dk, B_ * SK_, U_, U_);

    // 2) Raw scores into the attention-weights output region
    scores_kernel<<<dim3(SK_ / 256, SQ_ / TQ, B_), 256>>>(wv, attn);

    // 3) Softmax in place
    softmax_kernel<<<B_ * SQ_, 256>>>(attn);

    // 4) context = attn @ value (batched, M=128 N=256 K=1024)
    gemm_32x64<<<dim3(U_ / 64, SQ_ / 32, B_), 256>>>(
        attn, value, ctx, SQ_, U_, SK_,
        (long long)SQ_ * SK_, (long long)SK_ * U_, (long long)SQ_ * U_);
}

// round 6
// speedup vs baseline: 1.1742x; 1.1742x over previous
#include <cuda_runtime.h>
#include <cuda_bf16.h>
#include <math_constants.h>

#define B_  8
#define SQ_ 128
#define SK_ 1024
#define U_  256

// Scratch for projected q and k (allocation-free rule: __device__ globals)
__device__ float g_q[B_ * SQ_ * U_];   // 1 MB
__device__ float g_k[B_ * SK_ * U_];   // 8 MB

__device__ __forceinline__ float tanha(float x) {
    float y;
    asm("tanh.approx.f32 %0, %1;" : "=f"(y) : "f"(x));
    return y;
}

// ---------------------------------------------------------------------------
// tf32 helpers: 3-term split GEMM gives ~fp32 accuracy on tensor cores.
// ---------------------------------------------------------------------------
__device__ __forceinline__ void tf32_split(float x, float& hi, float& lo) {
    unsigned u;
    asm("cvt.rna.tf32.f32 %0, %1;" : "=r"(u) : "f"(x));
    hi = __uint_as_float(u);
    float l = x - hi;
    unsigned ul;
    asm("cvt.rna.tf32.f32 %0, %1;" : "=r"(ul) : "f"(l));
    lo = __uint_as_float(ul);
}

__device__ __forceinline__ void mma_tf32(float& d0, float& d1, float& d2, float& d3,
                                         unsigned a0, unsigned a1, unsigned a2, unsigned a3,
                                         unsigned b0, unsigned b1) {
    asm("mma.sync.aligned.m16n8k8.row.col.f32.tf32.tf32.f32 "
        "{%0,%1,%2,%3}, {%4,%5,%6,%7}, {%8,%9}, {%0,%1,%2,%3};"
        : "+f"(d0), "+f"(d1), "+f"(d2), "+f"(d3)
        : "r"(a0), "r"(a1), "r"(a2), "r"(a3), "r"(b0), "r"(b1));
}

// ---------------------------------------------------------------------------
// Tensor-core SGEMM, tf32 3-term split: C = A @ B (both row-major, f32).
// CTA tile: (32*IM) x 64, K-chunk 32. 8 warps as 2(m) x 4(n), warp tile
// (16*IM) x 16, each warp 16x8 mma fragments. Batched via blockIdx.z.
// Requires: M % (32*IM) == 0, N % 64 == 0, K % 32 == 0.
// ---------------------------------------------------------------------------
template <int IM>
__global__ void gemm_tc(const float* __restrict__ A, const float* __restrict__ Bm,
                        float* __restrict__ C, int M, int N, int K,
                        long long sA, long long sB, long long sC) {
    constexpr int TM = 32 * IM;
    A  += (long long)blockIdx.z * sA;
    Bm += (long long)blockIdx.z * sB;
    C  += (long long)blockIdx.z * sC;

    __shared__ float Ah[TM][36], Al[TM][36];   // pad 36: frag loads conflict-free
    __shared__ float Bh[32][72], Bl[32][72];   // pad 72: frag loads conflict-free

    const int tid  = threadIdx.x;
    const int lane = tid & 31;
    const int warp = tid >> 5;
    const int wm   = warp >> 2;          // 0..1
    const int wn   = warp & 3;           // 0..3
    const int gid  = lane >> 2;          // 0..7
    const int tig  = lane & 3;           // 0..3
    const int m_base = wm * (16 * IM);
    const int n_base = wn * 16;

    const int m0 = blockIdx.y * TM;
    const int n0 = blockIdx.x * 64;

    float acc[IM][2][4];
#pragma unroll
    for (int im = 0; im < IM; im++)
#pragma unroll
        for (int in = 0; in < 2; in++)
#pragma unroll
            for (int c = 0; c < 4; c++) acc[im][in][c] = 0.0f;

    for (int k0 = 0; k0 < K; k0 += 32) {
        // ---- fill A tile (TM x 32) with hi/lo split ----
#pragma unroll
        for (int it = 0; it < (TM * 8) / 256; it++) {
            int idx = tid + it * 256;
            int r = idx >> 3;
            int c = (idx & 7) << 2;
            float4 v = *(const float4*)&A[(long long)(m0 + r) * K + k0 + c];
            float h0, l0, h1, l1, h2, l2, h3, l3;
            tf32_split(v.x, h0, l0); tf32_split(v.y, h1, l1);
            tf32_split(v.z, h2, l2); tf32_split(v.w, h3, l3);
            *(float4*)&Ah[r][c] = make_float4(h0, h1, h2, h3);
            *(float4*)&Al[r][c] = make_float4(l0, l1, l2, l3);
        }
        // ---- fill B tile (32 x 64) with hi/lo split ----
#pragma unroll
        for (int it = 0; it < 2; it++) {
            int idx = tid + it * 256;
            int r = idx >> 4;
            int c = (idx & 15) << 2;
            float4 v = *(const float4*)&Bm[(long long)(k0 + r) * N + n0 + c];
            float h0, l0, h1, l1, h2, l2, h3, l3;
            tf32_split(v.x, h0, l0); tf32_split(v.y, h1, l1);
            tf32_split(v.z, h2, l2); tf32_split(v.w, h3, l3);
            *(float4*)&Bh[r][c] = make_float4(h0, h1, h2, h3);
            *(float4*)&Bl[r][c] = make_float4(l0, l1, l2, l3);
        }
        __syncthreads();

#pragma unroll
        for (int kk = 0; kk < 4; kk++) {
            const int kb = kk * 8;
            // A fragments (hi and lo) per m-subtile
            unsigned ah[IM][4], al[IM][4];
#pragma unroll
            for (int im = 0; im < IM; im++) {
                int r0 = m_base + 16 * im + gid;
                ah[im][0] = __float_as_uint(Ah[r0    ][kb + tig    ]);
                ah[im][1] = __float_as_uint(Ah[r0 + 8][kb + tig    ]);
                ah[im][2] = __float_as_uint(Ah[r0    ][kb + tig + 4]);
                ah[im][3] = __float_as_uint(Ah[r0 + 8][kb + tig + 4]);
                al[im][0] = __float_as_uint(Al[r0    ][kb + tig    ]);
                al[im][1] = __float_as_uint(Al[r0 + 8][kb + tig    ]);
                al[im][2] = __float_as_uint(Al[r0    ][kb + tig + 4]);
                al[im][3] = __float_as_uint(Al[r0 + 8][kb + tig + 4]);
            }
            // B fragments (hi and lo) per n-subtile
            unsigned bh[2][2], bl[2][2];
#pragma unroll
            for (int in = 0; in < 2; in++) {
                int c0 = n_base + 8 * in + gid;
                bh[in][0] = __float_as_uint(Bh[kb + tig    ][c0]);
                bh[in][1] = __float_as_uint(Bh[kb + tig + 4][c0]);
                bl[in][0] = __float_as_uint(Bl[kb + tig    ][c0]);
                bl[in][1] = __float_as_uint(Bl[kb + tig + 4][c0]);
            }
#pragma unroll
            for (int im = 0; im < IM; im++)
#pragma unroll
                for (int in = 0; in < 2; in++) {
                    float* d = acc[im][in];
                    mma_tf32(d[0], d[1], d[2], d[3],
                             ah[im][0], ah[im][1], ah[im][2], ah[im][3],
                             bh[in][0], bh[in][1]);
                    mma_tf32(d[0], d[1], d[2], d[3],
                             ah[im][0], ah[im][1], ah[im][2], ah[im][3],
                             bl[in][0], bl[in][1]);
                    mma_tf32(d[0], d[1], d[2], d[3],
                             al[im][0], al[im][1], al[im][2], al[im][3],
                             bh[in][0], bh[in][1]);
                }
        }
        __syncthreads();
    }

    // ---- epilogue ----
#pragma unroll
    for (int im = 0; im < IM; im++) {
#pragma unroll
        for (int in = 0; in < 2; in++) {
            int row = m0 + m_base + 16 * im + gid;
            int col = n0 + n_base + 8 * in + 2 * tig;
            float* d = acc[im][in];
            *(float2*)&C[(long long)row * N + col]       = make_float2(d[0], d[1]);
            *(float2*)&C[(long long)(row + 8) * N + col] = make_float2(d[2], d[3]);
        }
    }
}

// ---------------------------------------------------------------------------
// Scores (f32 tanh, R4 version): j-column per thread, k in registers
// (double-buffered), q via broadcast LDS.
// score[b,i,j] = sum_u tanh(q[b,i,u] + k[b,j,u]) * wv[u]
// ---------------------------------------------------------------------------
#define TQ 16

__global__ void scores_kernel(const float* __restrict__ wv, float* __restrict__ attn) {
    const int b  = blockIdx.z;
    const int ib = blockIdx.y;
    const int tid = threadIdx.x;
    const int j  = blockIdx.x * 256 + tid;

    __shared__ float qs[TQ][U_];   // 16 KB
    __shared__ float wvs[U_];

    const float* qbase = g_q + ((long long)(b * SQ_ + ib * TQ)) * U_;
#pragma unroll
    for (int l = 0; l < 4; l++) {
        int idx = tid + l * 256;
        int row = idx >> 6;
        int col = (idx & 63) << 2;
        *(float4*)&qs[row][col] = *(const float4*)&qbase[(long long)row * U_ + col];
    }
    if (tid < 64) *(float4*)&wvs[tid << 2] = *(const float4*)&wv[tid << 2];
    __syncthreads();

    const float* kp = g_k + ((long long)(b * SK_) + j) * U_;

    float acc[TQ];
#pragma unroll
    for (int i = 0; i < TQ; i++) acc[i] = 0.0f;

    float4 ka = *(const float4*)&kp[0];
    float4 kb = *(const float4*)&kp[4];

#pragma unroll 4
    for (int uc = 0; uc < U_; uc += 8) {
        int un = (uc + 8 < U_) ? uc + 8 : uc;   // clamped tail prefetch
        float4 kna = *(const float4*)&kp[un];
        float4 knb = *(const float4*)&kp[un + 4];
        float4 w0 = *(const float4*)&wvs[uc];
        float4 w1 = *(const float4*)&wvs[uc + 4];
#pragma unroll
        for (int i = 0; i < TQ; i++) {
            float4 q0 = *(const float4*)&qs[i][uc];        // broadcast LDS
            float4 q1 = *(const float4*)&qs[i][uc + 4];    // broadcast LDS
            float s;
            s  = tanha(q0.x + ka.x) * w0.x;
            s += tanha(q0.y + ka.y) * w0.y;
            s += tanha(q0.z + ka.z) * w0.z;
            s += tanha(q0.w + ka.w) * w0.w;
            s += tanha(q1.x + kb.x) * w1.x;
            s += tanha(q1.y + kb.y) * w1.y;
            s += tanha(q1.z + kb.z) * w1.z;
            s += tanha(q1.w + kb.w) * w1.w;
            acc[i] += s;
        }
        ka = kna;
        kb = knb;
    }

    long long base = ((long long)(b * SQ_ + ib * TQ)) * SK_ + j;
#pragma unroll
    for (int i = 0; i < TQ; i++) attn[base + (long long)i * SK_] = acc[i];
}

// ---------------------------------------------------------------------------
// Row softmax over SK=1024, in place. One CTA (256 threads) per (b,i) row.
// ---------------------------------------------------------------------------
__global__ void softmax_kernel(float* __restrict__ attn) {
    float* p = attn + (long long)blockIdx.x * SK_;
    const int tid = threadIdx.x;
    __shared__ float red[8];

    float4 x = *(const float4*)&p[tid << 2];
    float m = fmaxf(fmaxf(x.x, x.y), fmaxf(x.z, x.w));
#pragma unroll
    for (int o = 16; o; o >>= 1) m = fmaxf(m, __shfl_xor_sync(0xffffffffu, m, o));
    if ((tid & 31) == 0) red[tid >> 5] = m;
    __syncthreads();
    float M = red[0];
#pragma unroll
    for (int w = 1; w < 8; w++) M = fmaxf(M, red[w]);

    float4 e;
    e.x = __expf(x.x - M);
    e.y = __expf(x.y - M);
    e.z = __expf(x.z - M);
    e.w = __expf(x.w - M);
    float s = (e.x + e.y) + (e.z + e.w);
#pragma unroll
    for (int o = 16; o; o >>= 1) s += __shfl_xor_sync(0xffffffffu, s, o);
    __syncthreads();
    if ((tid & 31) == 0) red[tid >> 5] = s;
    __syncthreads();
    float S = 0.f;
#pragma unroll
    for (int w = 0; w < 8; w++) S += red[w];
    float inv = 1.0f / S;
    e.x *= inv; e.y *= inv; e.z *= inv; e.w *= inv;
    *(float4*)&p[tid << 2] = e;
}

// ---------------------------------------------------------------------------
extern "C" void kernel_launch(void* const* d_in, const int* in_sizes, int n_in,
                              void* d_out, int out_size) {
    const float* query = (const float*)d_in[0];
    const float* key   = (const float*)d_in[1];
    const float* value = (const float*)d_in[2];
    const float* Wq    = (const float*)d_in[3];
    const float* Wk    = (const float*)d_in[4];
    const float* wv    = (const float*)d_in[5];

    float* out  = (float*)d_out;
    float* ctx  = out;                            // [B, SQ, U]
    float* attn = out + (long long)B_ * SQ_ * U_; // [B, SQ, SK]

    void* pq = nullptr; void* pk = nullptr;
    cudaGetSymbolAddress(&pq, g_q);
    cudaGetSymbolAddress(&pk, g_k);
    float* dq = (float*)pq;
    float* dk = (float*)pk;

    // 1) Projections on tensor cores (tf32 3-term split)
    //    q = query @ Wq : M=1024, N=256, K=256 -> 64 CTAs
    gemm_tc<2><<<dim3(U_ / 64, (B_ * SQ_) / 64, 1), 256>>>(
        query, Wq, dq, B_ * SQ_, U_, U_, 0, 0, 0);
    //    k = key @ Wk   : M=8192, N=256, K=256 -> 512 CTAs
    gemm_tc<2><<<dim3(U_ / 64, (B_ * SK_) / 64, 1), 256>>>(
        key, Wk, dk, B_ * SK_, U_, U_, 0, 0, 0);

    // 2) Raw scores into the attention-weights output region
    scores_kernel<<<dim3(SK_ / 256, SQ_ / TQ, B_), 256>>>(wv, attn);

    // 3) Softmax in place
    softmax_kernel<<<B_ * SQ_, 256>>>(attn);

    // 4) context = attn @ value (batched, M=128 N=256 K=1024): 32-row tiles
    gemm_tc<1><<<dim3(U_ / 64, SQ_ / 32, B_), 256>>>(
        attn, value, ctx, SQ_, U_, SK_,
        (long long)SQ_ * SK_, (long long)SK_ * U_, (long long)SQ_ * U_);
}